// round 1
// baseline (speedup 1.0000x reference)
#include <cuda_runtime.h>
#include <cuda_bf16.h>

// Problem: AttWModel — N=1024, L=2048, D=128
// out[n] = sum_l softmax_l( X[n,l]·(W^T z[n]) ) * ( X[n,l]·v )
//
// Pure streaming kernel: read input_seq (1 GiB) once; everything else is tiny.

#define NB   1024
#define LSEQ 2048
#define DIM  128
#define NW   8          // warps per block in main kernel

// Scratch for q[n] = W^T z[n]  (no cudaMalloc allowed)
__device__ float g_q[NB * DIM];

// ---------------------------------------------------------------------------
// Kernel 1: q[n,d] = sum_e z[n,e] * W[e,d]      (W row-major [D,D])
// grid = NB blocks, 128 threads; W is 64 KB -> L2 resident across all blocks.
// ---------------------------------------------------------------------------
__global__ void __launch_bounds__(DIM) compute_q_kernel(
    const float* __restrict__ z, const float* __restrict__ W)
{
    const int n = blockIdx.x;
    const int d = threadIdx.x;

    __shared__ float zs[DIM];
    zs[d] = z[n * DIM + d];
    __syncthreads();

    float a0 = 0.f, a1 = 0.f, a2 = 0.f, a3 = 0.f;
#pragma unroll
    for (int e = 0; e < DIM; e += 4) {
        a0 = fmaf(zs[e + 0], W[(e + 0) * DIM + d], a0);
        a1 = fmaf(zs[e + 1], W[(e + 1) * DIM + d], a1);
        a2 = fmaf(zs[e + 2], W[(e + 2) * DIM + d], a2);
        a3 = fmaf(zs[e + 3], W[(e + 3) * DIM + d], a3);
    }
    g_q[n * DIM + d] = (a0 + a1) + (a2 + a3);
}

// ---------------------------------------------------------------------------
// Kernel 2: streaming attention. One block per n. 8 warps; warp-per-row with
// 2-row unroll. Online softmax per warp; 8-way merge in smem.
// ---------------------------------------------------------------------------
__global__ void __launch_bounds__(NW * 32) attw_stream_kernel(
    const float* __restrict__ X,      // [NB, LSEQ, DIM]
    const float* __restrict__ v,      // [DIM]
    float* __restrict__ out)          // [NB]
{
    const int n    = blockIdx.x;
    const int lane = threadIdx.x & 31;
    const int wid  = threadIdx.x >> 5;

    // Per-lane 4-element chunks of q[n] and v (DIM=128 = 32 lanes * float4)
    const float4 q4 = reinterpret_cast<const float4*>(g_q + n * DIM)[lane];
    const float4 v4 = reinterpret_cast<const float4*>(v)[lane];

    const float4* Xn = reinterpret_cast<const float4*>(
        X + (size_t)n * LSEQ * DIM);   // row stride = 32 float4

    float m = -1e30f, Z = 0.f, num = 0.f;

    // Each warp handles rows {wid, wid+NW, wid+2NW, ...}; unroll 2 rows/iter.
#pragma unroll 1
    for (int l = wid; l < LSEQ; l += 2 * NW) {
        const float4 x0 = Xn[l * 32 + lane];
        const float4 x1 = Xn[(l + NW) * 32 + lane];

        float s0 = x0.x * q4.x + x0.y * q4.y + x0.z * q4.z + x0.w * q4.w;
        float t0 = x0.x * v4.x + x0.y * v4.y + x0.z * v4.z + x0.w * v4.w;
        float s1 = x1.x * q4.x + x1.y * q4.y + x1.z * q4.z + x1.w * q4.w;
        float t1 = x1.x * v4.x + x1.y * v4.y + x1.z * v4.z + x1.w * v4.w;

#pragma unroll
        for (int off = 16; off > 0; off >>= 1) {
            s0 += __shfl_xor_sync(0xffffffffu, s0, off);
            t0 += __shfl_xor_sync(0xffffffffu, t0, off);
            s1 += __shfl_xor_sync(0xffffffffu, s1, off);
            t1 += __shfl_xor_sync(0xffffffffu, t1, off);
        }

        // Online-softmax update with both rows at once (state replicated per lane)
        const float mn = fmaxf(m, fmaxf(s0, s1));
        const float sc = expf(m - mn);
        const float p0 = expf(s0 - mn);
        const float p1 = expf(s1 - mn);
        Z   = Z   * sc + p0 + p1;
        num = num * sc + p0 * t0 + p1 * t1;
        m = mn;
    }

    // Merge the 8 per-warp online-softmax states
    __shared__ float sm[NW], sZ[NW], sN[NW];
    if (lane == 0) { sm[wid] = m; sZ[wid] = Z; sN[wid] = num; }
    __syncthreads();

    if (threadIdx.x == 0) {
        float M = sm[0];
#pragma unroll
        for (int w = 1; w < NW; w++) M = fmaxf(M, sm[w]);
        float Zt = 0.f, Nt = 0.f;
#pragma unroll
        for (int w = 0; w < NW; w++) {
            const float sc = expf(sm[w] - M);
            Zt += sZ[w] * sc;
            Nt += sN[w] * sc;
        }
        out[n] = Nt / Zt;
    }
}

// ---------------------------------------------------------------------------
// kernel_launch — inputs per metadata order:
//   d_in[0] = input_seq  [N, L, D] f32
//   d_in[1] = cross_input [N, D]   f32
//   d_in[2] = W           [D, D]   f32
//   d_in[3] = v           [D]      f32
// d_out = [N, 1] f32
// ---------------------------------------------------------------------------
extern "C" void kernel_launch(void* const* d_in, const int* in_sizes, int n_in,
                              void* d_out, int out_size)
{
    const float* X = (const float*)d_in[0];
    const float* z = (const float*)d_in[1];
    const float* W = (const float*)d_in[2];
    const float* v = (const float*)d_in[3];
    float* out = (float*)d_out;

    compute_q_kernel<<<NB, DIM>>>(z, W);
    attw_stream_kernel<<<NB, NW * 32>>>(X, v, out);
}